// round 6
// baseline (speedup 1.0000x reference)
#include <cuda_runtime.h>
#include <math.h>

#define BB 32
#define TT 1024
#define DD 512
#define KK 64
#define OO 1024
#define F_EPS 1e-12f

typedef unsigned long long ull;

__device__ __forceinline__ ull pack2(float v) {
    ull r;
    asm("mov.b64 %0, {%1, %1};" : "=l"(r) : "f"(v));
    return r;
}
__device__ __forceinline__ void ffma2(ull& d, ull a, ull b) {
    asm("fma.rn.f32x2 %0, %1, %2, %0;" : "+l"(d) : "l"(a), "l"(b));
}
__device__ __forceinline__ float2 unpack2(ull v) {
    float2 f;
    asm("mov.b64 {%0, %1}, %2;" : "=f"(f.x), "=f"(f.y) : "l"(v));
    return f;
}

// Scratch
__device__ float g_a[BB * TT * KK];      // soft-assign [B,T,K]
__device__ float g_agg[BB * KK * DD];    // x_agg [B,K,D]
__device__ float g_vt[KK * DD * BB];     // normalized v, transposed [kd][b]
__device__ float g_sumw[BB * KK];
__device__ float g_norm2[BB];

// ---------------------------------------------------------------------------
// K1: logits = x@W + bias -> softmax -> a, sum_w.
// Block: 128 rows x 64 k, 256 threads, thread tile 4r x 8k (pairs along k).
// ---------------------------------------------------------------------------
__global__ __launch_bounds__(256) void k_assign(const float* __restrict__ x,
                                                const float* __restrict__ w,
                                                const float* __restrict__ bias) {
    __shared__ __align__(16) float xs_t[2][16 * 132];  // [d][r], pad 132
    __shared__ __align__(16) float ws[2][16 * 68];     // [d][k], pad 68
    __shared__ float bias_s[64];
    __shared__ float ssum[64];

    const int tid = threadIdx.x;
    const int r0 = blockIdx.x * 128;
    const int kq = tid & 7;       // k = kq*8 + j
    const int rq = tid >> 3;      // r = r0 + rq*4 + i   (32 groups)
    const int b  = r0 >> 10;

    if (tid < 64) { ssum[tid] = 0.0f; bias_s[tid] = bias[tid]; }

    ull acc2[4][4];
#pragma unroll
    for (int i = 0; i < 4; i++)
#pragma unroll
        for (int j = 0; j < 4; j++) acc2[i][j] = 0ull;

    float4 px[2], pw;

#define K1_LDG(d0)                                                              \
    do {                                                                        \
        _Pragma("unroll")                                                       \
        for (int i_ = 0; i_ < 2; i_++) {                                        \
            int idx = tid + i_ * 256;                                           \
            int row = idx >> 2, dc = (idx & 3) * 4;                             \
            px[i_] = *(const float4*)&x[(size_t)(r0 + row) * DD + (d0) + dc];   \
        }                                                                       \
        {                                                                       \
            int dl = tid >> 4, kc = (tid & 15) * 4;                             \
            pw = *(const float4*)&w[(size_t)((d0) + dl) * KK + kc];             \
        }                                                                       \
    } while (0)

#define K1_STS(p)                                                               \
    do {                                                                        \
        _Pragma("unroll")                                                       \
        for (int i_ = 0; i_ < 2; i_++) {                                        \
            int idx = tid + i_ * 256;                                           \
            int row = idx >> 2, dc = (idx & 3) * 4;                             \
            xs_t[p][(dc + 0) * 132 + row] = px[i_].x;                           \
            xs_t[p][(dc + 1) * 132 + row] = px[i_].y;                           \
            xs_t[p][(dc + 2) * 132 + row] = px[i_].z;                           \
            xs_t[p][(dc + 3) * 132 + row] = px[i_].w;                           \
        }                                                                       \
        {                                                                       \
            int dl = tid >> 4, kc = (tid & 15) * 4;                             \
            *(float4*)&ws[p][dl * 68 + kc] = pw;                                \
        }                                                                       \
    } while (0)

    K1_LDG(0);
    K1_STS(0);
    __syncthreads();

    const int NC = DD / 16;   // 32 chunks
    for (int c = 0; c < NC; c++) {
        const int cur = c & 1;
        if (c + 1 < NC) K1_LDG((c + 1) * 16);

#pragma unroll
        for (int d = 0; d < 16; d++) {
            ulonglong2 w01 = *(const ulonglong2*)&ws[cur][d * 68 + kq * 8];
            ulonglong2 w23 = *(const ulonglong2*)&ws[cur][d * 68 + kq * 8 + 4];
            float4 x0 = *(const float4*)&xs_t[cur][d * 132 + rq * 4];
            ull xp[4];
            xp[0] = pack2(x0.x); xp[1] = pack2(x0.y);
            xp[2] = pack2(x0.z); xp[3] = pack2(x0.w);
#pragma unroll
            for (int i = 0; i < 4; i++) {
                ffma2(acc2[i][0], xp[i], w01.x);
                ffma2(acc2[i][1], xp[i], w01.y);
                ffma2(acc2[i][2], xp[i], w23.x);
                ffma2(acc2[i][3], xp[i], w23.y);
            }
        }
        if (c + 1 < NC) K1_STS(cur ^ 1);
        __syncthreads();
    }
#undef K1_LDG
#undef K1_STS

    // softmax per row: 64 logits over 8 lanes (kq) x 8 regs
    float colsum[8];
#pragma unroll
    for (int j = 0; j < 8; j++) colsum[j] = 0.0f;
#pragma unroll
    for (int i = 0; i < 4; i++) {
        float v[8];
#pragma unroll
        for (int j = 0; j < 4; j++) {
            float2 p = unpack2(acc2[i][j]);
            v[j * 2 + 0] = p.x;
            v[j * 2 + 1] = p.y;
        }
        float m = -1e30f;
#pragma unroll
        for (int j = 0; j < 8; j++) {
            v[j] += bias_s[kq * 8 + j];
            m = fmaxf(m, v[j]);
        }
#pragma unroll
        for (int off = 4; off > 0; off >>= 1)
            m = fmaxf(m, __shfl_xor_sync(0xffffffffu, m, off));
        float s = 0.0f;
#pragma unroll
        for (int j = 0; j < 8; j++) { v[j] = __expf(v[j] - m); s += v[j]; }
#pragma unroll
        for (int off = 4; off > 0; off >>= 1)
            s += __shfl_xor_sync(0xffffffffu, s, off);
        float inv = 1.0f / s;
        float4 a0, a1;
        a0.x = v[0] * inv; a0.y = v[1] * inv; a0.z = v[2] * inv; a0.w = v[3] * inv;
        a1.x = v[4] * inv; a1.y = v[5] * inv; a1.z = v[6] * inv; a1.w = v[7] * inv;
        colsum[0] += a0.x; colsum[1] += a0.y; colsum[2] += a0.z; colsum[3] += a0.w;
        colsum[4] += a1.x; colsum[5] += a1.y; colsum[6] += a1.z; colsum[7] += a1.w;
        size_t row = (size_t)(r0 + rq * 4 + i);
        *(float4*)&g_a[row * KK + kq * 8] = a0;
        *(float4*)&g_a[row * KK + kq * 8 + 4] = a1;
    }

    // reduce over the 4 rq groups inside each warp (tid bits 3,4)
#pragma unroll
    for (int j = 0; j < 8; j++) {
        colsum[j] += __shfl_xor_sync(0xffffffffu, colsum[j], 8);
        colsum[j] += __shfl_xor_sync(0xffffffffu, colsum[j], 16);
    }
    if ((tid & 31) < 8) {
#pragma unroll
        for (int j = 0; j < 8; j++) atomicAdd(&ssum[kq * 8 + j], colsum[j]);
    }
    __syncthreads();
    if (tid < 64) atomicAdd(&g_sumw[b * KK + tid], ssum[tid]);
}

// ---------------------------------------------------------------------------
// K2: x_agg[b,k,d] = sum_t a[b,t,k] x[b,t,d]
// Block: 64k x 128d, 256 threads, thread tile 4k x 8d (pairs along d).
// grid: b(32) x dtile(4) x tseg(2) = 256 blocks; 512 t per block, chunk 16.
// ---------------------------------------------------------------------------
__global__ __launch_bounds__(256) void k_agg(const float* __restrict__ x) {
    __shared__ __align__(16) float as[2][16 * 68];    // [t][k]
    __shared__ __align__(16) float xs[2][16 * 132];   // [t][d]

    const int tid = threadIdx.x;
    const int bx = blockIdx.x;
    const int b   = bx >> 3;
    const int dt  = (bx >> 1) & 3;
    const int seg = bx & 1;
    const int t0  = seg * 512;
    const int kq  = tid >> 4;     // k = kq*4 + i   (16 groups)
    const int dq  = tid & 15;     // d = dt*128 + dq*8 + j pairs

    ull acc2[4][4];
#pragma unroll
    for (int i = 0; i < 4; i++)
#pragma unroll
        for (int j = 0; j < 4; j++) acc2[i][j] = 0ull;

    float4 pa, px[2];

#define K2_LDG(tb)                                                              \
    do {                                                                        \
        {                                                                       \
            int row = tid >> 4, col = (tid & 15) * 4;                           \
            pa = *(const float4*)&g_a[(size_t)(b * TT + (tb) + row) * KK + col];\
        }                                                                       \
        _Pragma("unroll")                                                       \
        for (int i_ = 0; i_ < 2; i_++) {                                        \
            int idx = tid + i_ * 256;                                           \
            int row = idx >> 5, col = (idx & 31) * 4;                           \
            px[i_] = *(const float4*)&x[(size_t)(b * TT + (tb) + row) * DD + dt * 128 + col]; \
        }                                                                       \
    } while (0)

#define K2_STS(p)                                                               \
    do {                                                                        \
        {                                                                       \
            int row = tid >> 4, col = (tid & 15) * 4;                           \
            *(float4*)&as[p][row * 68 + col] = pa;                              \
        }                                                                       \
        _Pragma("unroll")                                                       \
        for (int i_ = 0; i_ < 2; i_++) {                                        \
            int idx = tid + i_ * 256;                                           \
            int row = idx >> 5, col = (idx & 31) * 4;                           \
            *(float4*)&xs[p][row * 132 + col] = px[i_];                         \
        }                                                                       \
    } while (0)

    K2_LDG(t0);
    K2_STS(0);
    __syncthreads();

    const int NC = 512 / 16;   // 32 chunks
    for (int c = 0; c < NC; c++) {
        const int cur = c & 1;
        if (c + 1 < NC) K2_LDG(t0 + (c + 1) * 16);

#pragma unroll
        for (int t = 0; t < 16; t++) {
            float4 a0 = *(const float4*)&as[cur][t * 68 + kq * 4];
            ulonglong2 x01 = *(const ulonglong2*)&xs[cur][t * 132 + dq * 8];
            ulonglong2 x23 = *(const ulonglong2*)&xs[cur][t * 132 + dq * 8 + 4];
            ull ap[4];
            ap[0] = pack2(a0.x); ap[1] = pack2(a0.y);
            ap[2] = pack2(a0.z); ap[3] = pack2(a0.w);
#pragma unroll
            for (int i = 0; i < 4; i++) {
                ffma2(acc2[i][0], ap[i], x01.x);
                ffma2(acc2[i][1], ap[i], x01.y);
                ffma2(acc2[i][2], ap[i], x23.x);
                ffma2(acc2[i][3], ap[i], x23.y);
            }
        }
        if (c + 1 < NC) K2_STS(cur ^ 1);
        __syncthreads();
    }
#undef K2_LDG
#undef K2_STS

#pragma unroll
    for (int i = 0; i < 4; i++)
#pragma unroll
        for (int j = 0; j < 4; j++) {
            float2 p = unpack2(acc2[i][j]);
            size_t base = ((size_t)b * KK + kq * 4 + i) * DD + dt * 128 + dq * 8 + j * 2;
            atomicAdd(&g_agg[base + 0], p.x);
            atomicAdd(&g_agg[base + 1], p.y);
        }
}

// ---------------------------------------------------------------------------
// K3: residual + intra L2-normalize; write v transposed to g_vt[kd][b]
// ---------------------------------------------------------------------------
__global__ __launch_bounds__(128) void k_norm(const float* __restrict__ centers) {
    const int bx = blockIdx.x;                // 2048 = B*K
    const int b = bx >> 6;
    const int k = bx & 63;
    const int tid = threadIdx.x;

    const float sw = g_sumw[b * KK + k];
    const size_t base = ((size_t)b * KK + k) * DD;

    float4 xa = *(float4*)&g_agg[base + tid * 4];
    float4 c  = *(const float4*)&centers[(size_t)k * DD + tid * 4];
    float4 f;
    f.x = xa.x - sw * c.x;
    f.y = xa.y - sw * c.y;
    f.z = xa.z - sw * c.z;
    f.w = xa.w - sw * c.w;
    float ss = f.x * f.x + f.y * f.y + f.z * f.z + f.w * f.w;

#pragma unroll
    for (int off = 16; off > 0; off >>= 1)
        ss += __shfl_xor_sync(0xffffffffu, ss, off);

    __shared__ float wsum[4];
    __shared__ float scale_s;
    if ((tid & 31) == 0) wsum[tid >> 5] = ss;
    __syncthreads();
    if (tid == 0) {
        float tot = wsum[0] + wsum[1] + wsum[2] + wsum[3];
        float sc = rsqrtf(fmaxf(tot, F_EPS));
        scale_s = sc;
        atomicAdd(&g_norm2[b], tot * sc * sc);
    }
    __syncthreads();
    float sc = scale_s;
    const int d = tid * 4;
    const size_t vbase = ((size_t)k * DD + d) * BB + b;
    g_vt[vbase + 0 * BB] = f.x * sc;
    g_vt[vbase + 1 * BB] = f.y * sc;
    g_vt[vbase + 2 * BB] = f.z * sc;
    g_vt[vbase + 3 * BB] = f.w * sc;
}

// ---------------------------------------------------------------------------
// K4: out[b,o] += sum_kd v[b,kd] R[kd,o]     (kd total = 32768)
// Block: 32b x 256o, 256 threads, thread tile 8b(4 bpairs) x 4o, chunk 16.
// grid: o-tiles(4) x kd-splits(128 of 256 kd) = 512 blocks.
// ---------------------------------------------------------------------------
__global__ __launch_bounds__(256) void k_out(const float* __restrict__ R,
                                             float* __restrict__ out) {
    __shared__ __align__(16) float vs[2][16 * 36];    // [kd][b]
    __shared__ __align__(16) float rs[2][16 * 260];   // [kd][o]

    const int tid = threadIdx.x;
    const int bx = blockIdx.x;
    const int o0  = (bx & 3) * 256;
    const int kd0 = (bx >> 2) * 256;
    const int bq = tid >> 6;       // 4 groups of 8 b (4 bpairs)
    const int oq = tid & 63;       // o = o0 + oq*4 + j

    ull acc2[4][4];                // [bpair][o]
#pragma unroll
    for (int i = 0; i < 4; i++)
#pragma unroll
        for (int j = 0; j < 4; j++) acc2[i][j] = 0ull;

    float4 pv, pr[4];

#define K4_LDG(c_)                                                              \
    do {                                                                        \
        if (tid < 128) {                                                        \
            int row = tid >> 3, col = (tid & 7) * 4;                            \
            pv = *(const float4*)&g_vt[(size_t)(kd0 + (c_) * 16 + row) * BB + col]; \
        }                                                                       \
        _Pragma("unroll")                                                       \
        for (int i_ = 0; i_ < 4; i_++) {                                        \
            int idx = tid + i_ * 256;                                           \
            int row = idx >> 6, col = (idx & 63) * 4;                           \
            pr[i_] = *(const float4*)&R[(size_t)(kd0 + (c_) * 16 + row) * OO + o0 + col]; \
        }                                                                       \
    } while (0)

#define K4_STS(p)                                                               \
    do {                                                                        \
        if (tid < 128) {                                                        \
            int row = tid >> 3, col = (tid & 7) * 4;                            \
            *(float4*)&vs[p][row * 36 + col] = pv;                              \
        }                                                                       \
        _Pragma("unroll")                                                       \
        for (int i_ = 0; i_ < 4; i_++) {                                        \
            int idx = tid + i_ * 256;                                           \
            int row = idx >> 6, col = (idx & 63) * 4;                           \
            *(float4*)&rs[p][row * 260 + col] = pr[i_];                         \
        }                                                                       \
    } while (0)

    K4_LDG(0);
    K4_STS(0);
    __syncthreads();

    const int NC = 16;   // 16 chunks x 16 kd = 256 kd per block
    for (int c = 0; c < NC; c++) {
        const int cur = c & 1;
        if (c + 1 < NC) K4_LDG(c + 1);

#pragma unroll
        for (int kd = 0; kd < 16; kd++) {
            ulonglong2 v01 = *(const ulonglong2*)&vs[cur][kd * 36 + bq * 8];
            ulonglong2 v23 = *(const ulonglong2*)&vs[cur][kd * 36 + bq * 8 + 4];
            float4 rv = *(const float4*)&rs[cur][kd * 260 + oq * 4];
            ull rp[4];
            rp[0] = pack2(rv.x); rp[1] = pack2(rv.y);
            rp[2] = pack2(rv.z); rp[3] = pack2(rv.w);
#pragma unroll
            for (int j = 0; j < 4; j++) {
                ffma2(acc2[0][j], v01.x, rp[j]);
                ffma2(acc2[1][j], v01.y, rp[j]);
                ffma2(acc2[2][j], v23.x, rp[j]);
                ffma2(acc2[3][j], v23.y, rp[j]);
            }
        }
        if (c + 1 < NC) K4_STS(cur ^ 1);
        __syncthreads();
    }
#undef K4_LDG
#undef K4_STS

#pragma unroll
    for (int i = 0; i < 4; i++)
#pragma unroll
        for (int j = 0; j < 4; j++) {
            float2 p = unpack2(acc2[i][j]);   // pair along b
            int o = o0 + oq * 4 + j;
            atomicAdd(&out[(size_t)(bq * 8 + i * 2 + 0) * OO + o], p.x);
            atomicAdd(&out[(size_t)(bq * 8 + i * 2 + 1) * OO + o], p.y);
        }
}

// ---------------------------------------------------------------------------
// K5: apply second L2-normalize scale
// ---------------------------------------------------------------------------
__global__ __launch_bounds__(256) void k_finish(float* __restrict__ out) {
    int i = blockIdx.x * 256 + threadIdx.x;   // 32768 = B*O
    int b = i >> 10;
    out[i] *= rsqrtf(fmaxf(g_norm2[b], F_EPS));
}

extern "C" void kernel_launch(void* const* d_in, const int* in_sizes, int n_in,
                              void* d_out, int out_size) {
    const float* x       = (const float*)d_in[0];
    const float* w       = (const float*)d_in[1];
    const float* bias    = (const float*)d_in[2];
    const float* centers = (const float*)d_in[3];
    const float* R       = (const float*)d_in[4];
    float* out = (float*)d_out;

    void *p_agg, *p_sumw, *p_norm2;
    cudaGetSymbolAddress(&p_agg, g_agg);
    cudaGetSymbolAddress(&p_sumw, g_sumw);
    cudaGetSymbolAddress(&p_norm2, g_norm2);

    cudaMemsetAsync(p_agg, 0, sizeof(float) * BB * KK * DD);
    cudaMemsetAsync(p_sumw, 0, sizeof(float) * BB * KK);
    cudaMemsetAsync(p_norm2, 0, sizeof(float) * BB);
    cudaMemsetAsync(d_out, 0, sizeof(float) * BB * OO);

    k_assign<<<256, 256>>>(x, w, bias);
    k_agg<<<256, 256>>>(x);
    k_norm<<<2048, 128>>>(centers);
    k_out<<<512, 256>>>(R, out);
    k_finish<<<128, 256>>>(out);
}

// round 7
// speedup vs baseline: 1.0009x; 1.0009x over previous
#include <cuda_runtime.h>
#include <math.h>

#define BB 32
#define TT 1024
#define DD 512
#define KK 64
#define OO 1024
#define F_EPS 1e-12f

typedef unsigned long long ull;

__device__ __forceinline__ ull pack2(float v) {
    ull r;
    asm("mov.b64 %0, {%1, %1};" : "=l"(r) : "f"(v));
    return r;
}
__device__ __forceinline__ void ffma2(ull& d, ull a, ull b) {
    asm("fma.rn.f32x2 %0, %1, %2, %0;" : "+l"(d) : "l"(a), "l"(b));
}
__device__ __forceinline__ float2 unpack2(ull v) {
    float2 f;
    asm("mov.b64 {%0, %1}, %2;" : "=f"(f.x), "=f"(f.y) : "l"(v));
    return f;
}

// Scratch
__device__ float g_a[BB * TT * KK];      // soft-assign [B,T,K]
__device__ float g_agg[BB * KK * DD];    // x_agg [B,K,D]
__device__ float g_vt[KK * DD * BB];     // normalized v, transposed [kd][b]
__device__ float g_sumw[BB * KK];
__device__ float g_norm2[BB];

// ---------------------------------------------------------------------------
// K1: logits = x@W + bias -> softmax -> a, sum_w.
// Block: 128 rows x 64 k, 256 threads, thread tile 4r x 8k (pairs along k).
// ---------------------------------------------------------------------------
__global__ __launch_bounds__(256) void k_assign(const float* __restrict__ x,
                                                const float* __restrict__ w,
                                                const float* __restrict__ bias) {
    __shared__ __align__(16) float xs_t[2][16 * 132];  // [d][r], pad 132
    __shared__ __align__(16) float ws[2][16 * 68];     // [d][k], pad 68
    __shared__ float bias_s[64];
    __shared__ float ssum[64];

    const int tid = threadIdx.x;
    const int r0 = blockIdx.x * 128;
    const int kq = tid & 7;       // k = kq*8 + j
    const int rq = tid >> 3;      // r = r0 + rq*4 + i   (32 groups)
    const int b  = r0 >> 10;

    if (tid < 64) { ssum[tid] = 0.0f; bias_s[tid] = bias[tid]; }

    ull acc2[4][4];
#pragma unroll
    for (int i = 0; i < 4; i++)
#pragma unroll
        for (int j = 0; j < 4; j++) acc2[i][j] = 0ull;

    float4 px[2], pw;

#define K1_LDG(d0)                                                              \
    do {                                                                        \
        _Pragma("unroll")                                                       \
        for (int i_ = 0; i_ < 2; i_++) {                                        \
            int idx = tid + i_ * 256;                                           \
            int row = idx >> 2, dc = (idx & 3) * 4;                             \
            px[i_] = *(const float4*)&x[(size_t)(r0 + row) * DD + (d0) + dc];   \
        }                                                                       \
        {                                                                       \
            int dl = tid >> 4, kc = (tid & 15) * 4;                             \
            pw = *(const float4*)&w[(size_t)((d0) + dl) * KK + kc];             \
        }                                                                       \
    } while (0)

#define K1_STS(p)                                                               \
    do {                                                                        \
        _Pragma("unroll")                                                       \
        for (int i_ = 0; i_ < 2; i_++) {                                        \
            int idx = tid + i_ * 256;                                           \
            int row = idx >> 2, dc = (idx & 3) * 4;                             \
            xs_t[p][(dc + 0) * 132 + row] = px[i_].x;                           \
            xs_t[p][(dc + 1) * 132 + row] = px[i_].y;                           \
            xs_t[p][(dc + 2) * 132 + row] = px[i_].z;                           \
            xs_t[p][(dc + 3) * 132 + row] = px[i_].w;                           \
        }                                                                       \
        {                                                                       \
            int dl = tid >> 4, kc = (tid & 15) * 4;                             \
            *(float4*)&ws[p][dl * 68 + kc] = pw;                                \
        }                                                                       \
    } while (0)

    K1_LDG(0);
    K1_STS(0);
    __syncthreads();

    const int NC = DD / 16;   // 32 chunks
    for (int c = 0; c < NC; c++) {
        const int cur = c & 1;
        if (c + 1 < NC) K1_LDG((c + 1) * 16);

#pragma unroll
        for (int d = 0; d < 16; d++) {
            ulonglong2 w01 = *(const ulonglong2*)&ws[cur][d * 68 + kq * 8];
            ulonglong2 w23 = *(const ulonglong2*)&ws[cur][d * 68 + kq * 8 + 4];
            float4 x0 = *(const float4*)&xs_t[cur][d * 132 + rq * 4];
            ull xp[4];
            xp[0] = pack2(x0.x); xp[1] = pack2(x0.y);
            xp[2] = pack2(x0.z); xp[3] = pack2(x0.w);
#pragma unroll
            for (int i = 0; i < 4; i++) {
                ffma2(acc2[i][0], xp[i], w01.x);
                ffma2(acc2[i][1], xp[i], w01.y);
                ffma2(acc2[i][2], xp[i], w23.x);
                ffma2(acc2[i][3], xp[i], w23.y);
            }
        }
        if (c + 1 < NC) K1_STS(cur ^ 1);
        __syncthreads();
    }
#undef K1_LDG
#undef K1_STS

    // softmax per row: 64 logits over 8 lanes (kq) x 8 regs
    float colsum[8];
#pragma unroll
    for (int j = 0; j < 8; j++) colsum[j] = 0.0f;
#pragma unroll
    for (int i = 0; i < 4; i++) {
        float v[8];
#pragma unroll
        for (int j = 0; j < 4; j++) {
            float2 p = unpack2(acc2[i][j]);
            v[j * 2 + 0] = p.x;
            v[j * 2 + 1] = p.y;
        }
        float m = -1e30f;
#pragma unroll
        for (int j = 0; j < 8; j++) {
            v[j] += bias_s[kq * 8 + j];
            m = fmaxf(m, v[j]);
        }
#pragma unroll
        for (int off = 4; off > 0; off >>= 1)
            m = fmaxf(m, __shfl_xor_sync(0xffffffffu, m, off));
        float s = 0.0f;
#pragma unroll
        for (int j = 0; j < 8; j++) { v[j] = __expf(v[j] - m); s += v[j]; }
#pragma unroll
        for (int off = 4; off > 0; off >>= 1)
            s += __shfl_xor_sync(0xffffffffu, s, off);
        float inv = 1.0f / s;
        float4 a0, a1;
        a0.x = v[0] * inv; a0.y = v[1] * inv; a0.z = v[2] * inv; a0.w = v[3] * inv;
        a1.x = v[4] * inv; a1.y = v[5] * inv; a1.z = v[6] * inv; a1.w = v[7] * inv;
        colsum[0] += a0.x; colsum[1] += a0.y; colsum[2] += a0.z; colsum[3] += a0.w;
        colsum[4] += a1.x; colsum[5] += a1.y; colsum[6] += a1.z; colsum[7] += a1.w;
        size_t row = (size_t)(r0 + rq * 4 + i);
        *(float4*)&g_a[row * KK + kq * 8] = a0;
        *(float4*)&g_a[row * KK + kq * 8 + 4] = a1;
    }

    // reduce over the 4 rq groups inside each warp (tid bits 3,4)
#pragma unroll
    for (int j = 0; j < 8; j++) {
        colsum[j] += __shfl_xor_sync(0xffffffffu, colsum[j], 8);
        colsum[j] += __shfl_xor_sync(0xffffffffu, colsum[j], 16);
    }
    if ((tid & 31) < 8) {
#pragma unroll
        for (int j = 0; j < 8; j++) atomicAdd(&ssum[kq * 8 + j], colsum[j]);
    }
    __syncthreads();
    if (tid < 64) atomicAdd(&g_sumw[b * KK + tid], ssum[tid]);
}

// ---------------------------------------------------------------------------
// K2: x_agg[b,k,d] = sum_t a[b,t,k] x[b,t,d]
// Block: 64k x 128d, 256 threads, thread tile 4k x 8d (pairs along d).
// grid: b(32) x dtile(4) x tseg(2) = 256 blocks; 512 t per block, chunk 16.
// ---------------------------------------------------------------------------
__global__ __launch_bounds__(256) void k_agg(const float* __restrict__ x) {
    __shared__ __align__(16) float as[2][16 * 68];    // [t][k]
    __shared__ __align__(16) float xs[2][16 * 132];   // [t][d]

    const int tid = threadIdx.x;
    const int bx = blockIdx.x;
    const int b   = bx >> 3;
    const int dt  = (bx >> 1) & 3;
    const int seg = bx & 1;
    const int t0  = seg * 512;
    const int kq  = tid >> 4;     // k = kq*4 + i   (16 groups)
    const int dq  = tid & 15;     // d = dt*128 + dq*8 + j pairs

    ull acc2[4][4];
#pragma unroll
    for (int i = 0; i < 4; i++)
#pragma unroll
        for (int j = 0; j < 4; j++) acc2[i][j] = 0ull;

    float4 pa, px[2];

#define K2_LDG(tb)                                                              \
    do {                                                                        \
        {                                                                       \
            int row = tid >> 4, col = (tid & 15) * 4;                           \
            pa = *(const float4*)&g_a[(size_t)(b * TT + (tb) + row) * KK + col];\
        }                                                                       \
        _Pragma("unroll")                                                       \
        for (int i_ = 0; i_ < 2; i_++) {                                        \
            int idx = tid + i_ * 256;                                           \
            int row = idx >> 5, col = (idx & 31) * 4;                           \
            px[i_] = *(const float4*)&x[(size_t)(b * TT + (tb) + row) * DD + dt * 128 + col]; \
        }                                                                       \
    } while (0)

#define K2_STS(p)                                                               \
    do {                                                                        \
        {                                                                       \
            int row = tid >> 4, col = (tid & 15) * 4;                           \
            *(float4*)&as[p][row * 68 + col] = pa;                              \
        }                                                                       \
        _Pragma("unroll")                                                       \
        for (int i_ = 0; i_ < 2; i_++) {                                        \
            int idx = tid + i_ * 256;                                           \
            int row = idx >> 5, col = (idx & 31) * 4;                           \
            *(float4*)&xs[p][row * 132 + col] = px[i_];                         \
        }                                                                       \
    } while (0)

    K2_LDG(t0);
    K2_STS(0);
    __syncthreads();

    const int NC = 512 / 16;   // 32 chunks
    for (int c = 0; c < NC; c++) {
        const int cur = c & 1;
        if (c + 1 < NC) K2_LDG(t0 + (c + 1) * 16);

#pragma unroll
        for (int t = 0; t < 16; t++) {
            float4 a0 = *(const float4*)&as[cur][t * 68 + kq * 4];
            ulonglong2 x01 = *(const ulonglong2*)&xs[cur][t * 132 + dq * 8];
            ulonglong2 x23 = *(const ulonglong2*)&xs[cur][t * 132 + dq * 8 + 4];
            ull ap[4];
            ap[0] = pack2(a0.x); ap[1] = pack2(a0.y);
            ap[2] = pack2(a0.z); ap[3] = pack2(a0.w);
#pragma unroll
            for (int i = 0; i < 4; i++) {
                ffma2(acc2[i][0], ap[i], x01.x);
                ffma2(acc2[i][1], ap[i], x01.y);
                ffma2(acc2[i][2], ap[i], x23.x);
                ffma2(acc2[i][3], ap[i], x23.y);
            }
        }
        if (c + 1 < NC) K2_STS(cur ^ 1);
        __syncthreads();
    }
#undef K2_LDG
#undef K2_STS

#pragma unroll
    for (int i = 0; i < 4; i++)
#pragma unroll
        for (int j = 0; j < 4; j++) {
            float2 p = unpack2(acc2[i][j]);
            size_t base = ((size_t)b * KK + kq * 4 + i) * DD + dt * 128 + dq * 8 + j * 2;
            atomicAdd(&g_agg[base + 0], p.x);
            atomicAdd(&g_agg[base + 1], p.y);
        }
}

// ---------------------------------------------------------------------------
// K3: residual + intra L2-normalize; write v transposed to g_vt[kd][b]
// ---------------------------------------------------------------------------
__global__ __launch_bounds__(128) void k_norm(const float* __restrict__ centers) {
    const int bx = blockIdx.x;                // 2048 = B*K
    const int b = bx >> 6;
    const int k = bx & 63;
    const int tid = threadIdx.x;

    const float sw = g_sumw[b * KK + k];
    const size_t base = ((size_t)b * KK + k) * DD;

    float4 xa = *(float4*)&g_agg[base + tid * 4];
    float4 c  = *(const float4*)&centers[(size_t)k * DD + tid * 4];
    float4 f;
    f.x = xa.x - sw * c.x;
    f.y = xa.y - sw * c.y;
    f.z = xa.z - sw * c.z;
    f.w = xa.w - sw * c.w;
    float ss = f.x * f.x + f.y * f.y + f.z * f.z + f.w * f.w;

#pragma unroll
    for (int off = 16; off > 0; off >>= 1)
        ss += __shfl_xor_sync(0xffffffffu, ss, off);

    __shared__ float wsum[4];
    __shared__ float scale_s;
    if ((tid & 31) == 0) wsum[tid >> 5] = ss;
    __syncthreads();
    if (tid == 0) {
        float tot = wsum[0] + wsum[1] + wsum[2] + wsum[3];
        float sc = rsqrtf(fmaxf(tot, F_EPS));
        scale_s = sc;
        atomicAdd(&g_norm2[b], tot * sc * sc);
    }
    __syncthreads();
    float sc = scale_s;
    const int d = tid * 4;
    const size_t vbase = ((size_t)k * DD + d) * BB + b;
    g_vt[vbase + 0 * BB] = f.x * sc;
    g_vt[vbase + 1 * BB] = f.y * sc;
    g_vt[vbase + 2 * BB] = f.z * sc;
    g_vt[vbase + 3 * BB] = f.w * sc;
}

// ---------------------------------------------------------------------------
// K4: out[b,o] += sum_kd v[b,kd] R[kd,o]     (kd total = 32768)
// Block: 32b x 256o, 256 threads, thread tile 8b(4 bpairs) x 4o, chunk 16.
// grid: o-tiles(4) x kd-splits(128 of 256 kd) = 512 blocks.
// ---------------------------------------------------------------------------
__global__ __launch_bounds__(256) void k_out(const float* __restrict__ R,
                                             float* __restrict__ out) {
    __shared__ __align__(16) float vs[2][16 * 36];    // [kd][b]
    __shared__ __align__(16) float rs[2][16 * 260];   // [kd][o]

    const int tid = threadIdx.x;
    const int bx = blockIdx.x;
    const int o0  = (bx & 3) * 256;
    const int kd0 = (bx >> 2) * 256;
    const int bq = tid >> 6;       // 4 groups of 8 b (4 bpairs)
    const int oq = tid & 63;       // o = o0 + oq*4 + j

    ull acc2[4][4];                // [bpair][o]
#pragma unroll
    for (int i = 0; i < 4; i++)
#pragma unroll
        for (int j = 0; j < 4; j++) acc2[i][j] = 0ull;

    float4 pv, pr[4];

#define K4_LDG(c_)                                                              \
    do {                                                                        \
        if (tid < 128) {                                                        \
            int row = tid >> 3, col = (tid & 7) * 4;                            \
            pv = *(const float4*)&g_vt[(size_t)(kd0 + (c_) * 16 + row) * BB + col]; \
        }                                                                       \
        _Pragma("unroll")                                                       \
        for (int i_ = 0; i_ < 4; i_++) {                                        \
            int idx = tid + i_ * 256;                                           \
            int row = idx >> 6, col = (idx & 63) * 4;                           \
            pr[i_] = *(const float4*)&R[(size_t)(kd0 + (c_) * 16 + row) * OO + o0 + col]; \
        }                                                                       \
    } while (0)

#define K4_STS(p)                                                               \
    do {                                                                        \
        if (tid < 128) {                                                        \
            int row = tid >> 3, col = (tid & 7) * 4;                            \
            *(float4*)&vs[p][row * 36 + col] = pv;                              \
        }                                                                       \
        _Pragma("unroll")                                                       \
        for (int i_ = 0; i_ < 4; i_++) {                                        \
            int idx = tid + i_ * 256;                                           \
            int row = idx >> 6, col = (idx & 63) * 4;                           \
            *(float4*)&rs[p][row * 260 + col] = pr[i_];                         \
        }                                                                       \
    } while (0)

    K4_LDG(0);
    K4_STS(0);
    __syncthreads();

    const int NC = 16;   // 16 chunks x 16 kd = 256 kd per block
    for (int c = 0; c < NC; c++) {
        const int cur = c & 1;
        if (c + 1 < NC) K4_LDG(c + 1);

#pragma unroll
        for (int kd = 0; kd < 16; kd++) {
            ulonglong2 v01 = *(const ulonglong2*)&vs[cur][kd * 36 + bq * 8];
            ulonglong2 v23 = *(const ulonglong2*)&vs[cur][kd * 36 + bq * 8 + 4];
            float4 rv = *(const float4*)&rs[cur][kd * 260 + oq * 4];
            ull rp[4];
            rp[0] = pack2(rv.x); rp[1] = pack2(rv.y);
            rp[2] = pack2(rv.z); rp[3] = pack2(rv.w);
#pragma unroll
            for (int j = 0; j < 4; j++) {
                ffma2(acc2[0][j], v01.x, rp[j]);
                ffma2(acc2[1][j], v01.y, rp[j]);
                ffma2(acc2[2][j], v23.x, rp[j]);
                ffma2(acc2[3][j], v23.y, rp[j]);
            }
        }
        if (c + 1 < NC) K4_STS(cur ^ 1);
        __syncthreads();
    }
#undef K4_LDG
#undef K4_STS

#pragma unroll
    for (int i = 0; i < 4; i++)
#pragma unroll
        for (int j = 0; j < 4; j++) {
            float2 p = unpack2(acc2[i][j]);   // pair along b
            int o = o0 + oq * 4 + j;
            atomicAdd(&out[(size_t)(bq * 8 + i * 2 + 0) * OO + o], p.x);
            atomicAdd(&out[(size_t)(bq * 8 + i * 2 + 1) * OO + o], p.y);
        }
}

// ---------------------------------------------------------------------------
// K5: apply second L2-normalize scale
// ---------------------------------------------------------------------------
__global__ __launch_bounds__(256) void k_finish(float* __restrict__ out) {
    int i = blockIdx.x * 256 + threadIdx.x;   // 32768 = B*O
    int b = i >> 10;
    out[i] *= rsqrtf(fmaxf(g_norm2[b], F_EPS));
}

extern "C" void kernel_launch(void* const* d_in, const int* in_sizes, int n_in,
                              void* d_out, int out_size) {
    const float* x       = (const float*)d_in[0];
    const float* w       = (const float*)d_in[1];
    const float* bias    = (const float*)d_in[2];
    const float* centers = (const float*)d_in[3];
    const float* R       = (const float*)d_in[4];
    float* out = (float*)d_out;

    void *p_agg, *p_sumw, *p_norm2;
    cudaGetSymbolAddress(&p_agg, g_agg);
    cudaGetSymbolAddress(&p_sumw, g_sumw);
    cudaGetSymbolAddress(&p_norm2, g_norm2);

    cudaMemsetAsync(p_agg, 0, sizeof(float) * BB * KK * DD);
    cudaMemsetAsync(p_sumw, 0, sizeof(float) * BB * KK);
    cudaMemsetAsync(p_norm2, 0, sizeof(float) * BB);
    cudaMemsetAsync(d_out, 0, sizeof(float) * BB * OO);

    k_assign<<<256, 256>>>(x, w, bias);
    k_agg<<<256, 256>>>(x);
    k_norm<<<2048, 128>>>(centers);
    k_out<<<512, 256>>>(R, out);
    k_finish<<<128, 256>>>(out);
}

// round 9
// speedup vs baseline: 1.4029x; 1.4016x over previous
#include <cuda_runtime.h>
#include <math.h>

#define BB 32
#define TT 1024
#define DD 512
#define KK 64
#define OO 1024
#define KD (KK * DD)
#define F_EPS 1e-12f

typedef unsigned long long ull;

__device__ __forceinline__ ull pack2(float v) {
    ull r; asm("mov.b64 %0, {%1, %1};" : "=l"(r) : "f"(v)); return r;
}
__device__ __forceinline__ void ffma2(ull& d, ull a, ull b) {
    asm("fma.rn.f32x2 %0, %1, %2, %0;" : "+l"(d) : "l"(a), "l"(b));
}
__device__ __forceinline__ float2 unpack2(ull v) {
    float2 f; asm("mov.b64 {%0, %1}, %2;" : "=f"(f.x), "=f"(f.y) : "l"(v)); return f;
}
__device__ __forceinline__ float tf32_rna(float v) {
    float h; asm("cvt.rna.tf32.f32 %0, %1;" : "=f"(h) : "f"(v)); return h;
}

__device__ float g_a[BB * TT * KK];
__device__ float g_agg[BB * KK * DD];
__device__ float g_v64[64 * KD];     // rows 0-31: tf32-hi(v) per b; rows 32-63: residual
__device__ float g_sumw[BB * KK];
__device__ float g_norm2[BB];

// K1 (R5 proven config)
__global__ __launch_bounds__(128) void k_assign(const float* __restrict__ x,
                                                const float* __restrict__ w,
                                                const float* __restrict__ bias) {
    __shared__ __align__(16) float xs_t[2][16 * 132];
    __shared__ __align__(16) float ws[2][16 * 68];
    __shared__ float bias_s[64];
    __shared__ float ssum[64];

    const int tid = threadIdx.x;
    const int r0 = blockIdx.x * 128;
    const int kq = tid & 7;
    const int rq = tid >> 3;
    const int b  = r0 >> 10;

    if (tid < 64) { ssum[tid] = 0.0f; bias_s[tid] = bias[tid]; }

    ull acc2[8][4];
#pragma unroll
    for (int i = 0; i < 8; i++)
#pragma unroll
        for (int j = 0; j < 4; j++) acc2[i][j] = 0ull;
    float4 px[4], pw[2];

#define K1_LDG(d0)                                                              \
    do {                                                                        \
        _Pragma("unroll")                                                       \
        for (int i_ = 0; i_ < 4; i_++) {                                        \
            int idx = tid + i_ * 128;                                           \
            int row = idx >> 2, dc = (idx & 3) * 4;                             \
            px[i_] = *(const float4*)&x[(size_t)(r0 + row) * DD + (d0) + dc];   \
        }                                                                       \
        _Pragma("unroll")                                                       \
        for (int i_ = 0; i_ < 2; i_++) {                                        \
            int idx = tid + i_ * 128;                                           \
            int dl = idx >> 4, kc = (idx & 15) * 4;                             \
            pw[i_] = *(const float4*)&w[(size_t)((d0) + dl) * KK + kc];         \
        }                                                                       \
    } while (0)
#define K1_STS(p)                                                               \
    do {                                                                        \
        _Pragma("unroll")                                                       \
        for (int i_ = 0; i_ < 4; i_++) {                                        \
            int idx = tid + i_ * 128;                                           \
            int row = idx >> 2, dc = (idx & 3) * 4;                             \
            xs_t[p][(dc + 0) * 132 + row] = px[i_].x;                           \
            xs_t[p][(dc + 1) * 132 + row] = px[i_].y;                           \
            xs_t[p][(dc + 2) * 132 + row] = px[i_].z;                           \
            xs_t[p][(dc + 3) * 132 + row] = px[i_].w;                           \
        }                                                                       \
        _Pragma("unroll")                                                       \
        for (int i_ = 0; i_ < 2; i_++) {                                        \
            int idx = tid + i_ * 128;                                           \
            int dl = idx >> 4, kc = (idx & 15) * 4;                             \
            *(float4*)&ws[p][dl * 68 + kc] = pw[i_];                            \
        }                                                                       \
    } while (0)

    K1_LDG(0); K1_STS(0);
    __syncthreads();
    const int NC = DD / 16;
    for (int c = 0; c < NC; c++) {
        const int cur = c & 1;
        if (c + 1 < NC) K1_LDG((c + 1) * 16);
#pragma unroll
        for (int d = 0; d < 16; d++) {
            ulonglong2 w01 = *(const ulonglong2*)&ws[cur][d * 68 + kq * 8];
            ulonglong2 w23 = *(const ulonglong2*)&ws[cur][d * 68 + kq * 8 + 4];
            float4 x0 = *(const float4*)&xs_t[cur][d * 132 + rq * 8];
            float4 x1 = *(const float4*)&xs_t[cur][d * 132 + rq * 8 + 4];
            ull xp[8];
            xp[0] = pack2(x0.x); xp[1] = pack2(x0.y);
            xp[2] = pack2(x0.z); xp[3] = pack2(x0.w);
            xp[4] = pack2(x1.x); xp[5] = pack2(x1.y);
            xp[6] = pack2(x1.z); xp[7] = pack2(x1.w);
#pragma unroll
            for (int i = 0; i < 8; i++) {
                ffma2(acc2[i][0], xp[i], w01.x);
                ffma2(acc2[i][1], xp[i], w01.y);
                ffma2(acc2[i][2], xp[i], w23.x);
                ffma2(acc2[i][3], xp[i], w23.y);
            }
        }
        if (c + 1 < NC) K1_STS(cur ^ 1);
        __syncthreads();
    }
#undef K1_LDG
#undef K1_STS

    float colsum[8];
#pragma unroll
    for (int j = 0; j < 8; j++) colsum[j] = 0.0f;
#pragma unroll
    for (int i = 0; i < 8; i++) {
        float v[8];
#pragma unroll
        for (int j = 0; j < 4; j++) {
            float2 p = unpack2(acc2[i][j]);
            v[j * 2 + 0] = p.x; v[j * 2 + 1] = p.y;
        }
        float m = -1e30f;
#pragma unroll
        for (int j = 0; j < 8; j++) { v[j] += bias_s[kq * 8 + j]; m = fmaxf(m, v[j]); }
#pragma unroll
        for (int off = 4; off > 0; off >>= 1)
            m = fmaxf(m, __shfl_xor_sync(0xffffffffu, m, off));
        float s = 0.0f;
#pragma unroll
        for (int j = 0; j < 8; j++) { v[j] = __expf(v[j] - m); s += v[j]; }
#pragma unroll
        for (int off = 4; off > 0; off >>= 1)
            s += __shfl_xor_sync(0xffffffffu, s, off);
        float inv = 1.0f / s;
        float4 a0, a1;
        a0.x = v[0] * inv; a0.y = v[1] * inv; a0.z = v[2] * inv; a0.w = v[3] * inv;
        a1.x = v[4] * inv; a1.y = v[5] * inv; a1.z = v[6] * inv; a1.w = v[7] * inv;
        colsum[0] += a0.x; colsum[1] += a0.y; colsum[2] += a0.z; colsum[3] += a0.w;
        colsum[4] += a1.x; colsum[5] += a1.y; colsum[6] += a1.z; colsum[7] += a1.w;
        size_t row = (size_t)(r0 + rq * 8 + i);
        *(float4*)&g_a[row * KK + kq * 8] = a0;
        *(float4*)&g_a[row * KK + kq * 8 + 4] = a1;
    }
#pragma unroll
    for (int j = 0; j < 8; j++) {
        colsum[j] += __shfl_xor_sync(0xffffffffu, colsum[j], 8);
        colsum[j] += __shfl_xor_sync(0xffffffffu, colsum[j], 16);
    }
    if ((tid & 31) < 8) {
#pragma unroll
        for (int j = 0; j < 8; j++) atomicAdd(&ssum[kq * 8 + j], colsum[j]);
    }
    __syncthreads();
    if (tid < 64) atomicAdd(&g_sumw[b * KK + tid], ssum[tid]);
}

// K2 (R5 proven config)
__global__ __launch_bounds__(128) void k_agg(const float* __restrict__ x) {
    __shared__ __align__(16) float as[2][16 * 68];
    __shared__ __align__(16) float xs[2][16 * 132];

    const int tid = threadIdx.x;
    const int bx = blockIdx.x;
    const int b   = bx >> 3;
    const int dt  = (bx >> 1) & 3;
    const int seg = bx & 1;
    const int t0  = seg * 512;
    const int kq2 = tid >> 4;
    const int dq  = tid & 15;

    ull acc2[8][4];
#pragma unroll
    for (int i = 0; i < 8; i++)
#pragma unroll
        for (int j = 0; j < 4; j++) acc2[i][j] = 0ull;
    float4 pa[2], px[4];

#define K2_LDG(tb)                                                              \
    do {                                                                        \
        _Pragma("unroll")                                                       \
        for (int i_ = 0; i_ < 2; i_++) {                                        \
            int idx = tid + i_ * 128;                                           \
            int row = idx >> 4, col = (idx & 15) * 4;                           \
            pa[i_] = *(const float4*)&g_a[(size_t)(b * TT + (tb) + row) * KK + col]; \
        }                                                                       \
        _Pragma("unroll")                                                       \
        for (int i_ = 0; i_ < 4; i_++) {                                        \
            int idx = tid + i_ * 128;                                           \
            int row = idx >> 5, col = (idx & 31) * 4;                           \
            px[i_] = *(const float4*)&x[(size_t)(b * TT + (tb) + row) * DD + dt * 128 + col]; \
        }                                                                       \
    } while (0)
#define K2_STS(p)                                                               \
    do {                                                                        \
        _Pragma("unroll")                                                       \
        for (int i_ = 0; i_ < 2; i_++) {                                        \
            int idx = tid + i_ * 128;                                           \
            int row = idx >> 4, col = (idx & 15) * 4;                           \
            *(float4*)&as[p][row * 68 + col] = pa[i_];                          \
        }                                                                       \
        _Pragma("unroll")                                                       \
        for (int i_ = 0; i_ < 4; i_++) {                                        \
            int idx = tid + i_ * 128;                                           \
            int row = idx >> 5, col = (idx & 31) * 4;                           \
            *(float4*)&xs[p][row * 132 + col] = px[i_];                         \
        }                                                                       \
    } while (0)

    K2_LDG(t0); K2_STS(0);
    __syncthreads();
    const int NC = 512 / 16;
    for (int c = 0; c < NC; c++) {
        const int cur = c & 1;
        if (c + 1 < NC) K2_LDG(t0 + (c + 1) * 16);
#pragma unroll
        for (int t = 0; t < 16; t++) {
            float4 a0 = *(const float4*)&as[cur][t * 68 + kq2 * 8];
            float4 a1 = *(const float4*)&as[cur][t * 68 + kq2 * 8 + 4];
            ulonglong2 x01 = *(const ulonglong2*)&xs[cur][t * 132 + dq * 8];
            ulonglong2 x23 = *(const ulonglong2*)&xs[cur][t * 132 + dq * 8 + 4];
            ull ap[8];
            ap[0] = pack2(a0.x); ap[1] = pack2(a0.y);
            ap[2] = pack2(a0.z); ap[3] = pack2(a0.w);
            ap[4] = pack2(a1.x); ap[5] = pack2(a1.y);
            ap[6] = pack2(a1.z); ap[7] = pack2(a1.w);
#pragma unroll
            for (int i = 0; i < 8; i++) {
                ffma2(acc2[i][0], ap[i], x01.x);
                ffma2(acc2[i][1], ap[i], x01.y);
                ffma2(acc2[i][2], ap[i], x23.x);
                ffma2(acc2[i][3], ap[i], x23.y);
            }
        }
        if (c + 1 < NC) K2_STS(cur ^ 1);
        __syncthreads();
    }
#undef K2_LDG
#undef K2_STS

#pragma unroll
    for (int i = 0; i < 8; i++)
#pragma unroll
        for (int j = 0; j < 4; j++) {
            float2 p = unpack2(acc2[i][j]);
            size_t base = ((size_t)b * KK + kq2 * 8 + i) * DD + dt * 128 + dq * 8 + j * 2;
            atomicAdd(&g_agg[base + 0], p.x);
            atomicAdd(&g_agg[base + 1], p.y);
        }
}

// K3: residual + intra-normalize; write tf32-hi / residual split rows of v
__global__ __launch_bounds__(128) void k_norm(const float* __restrict__ centers) {
    const int bx = blockIdx.x;
    const int b = bx >> 6;
    const int k = bx & 63;
    const int tid = threadIdx.x;

    const float sw = g_sumw[b * KK + k];
    const size_t base = ((size_t)b * KK + k) * DD;

    float4 xa = *(float4*)&g_agg[base + tid * 4];
    float4 c  = *(const float4*)&centers[(size_t)k * DD + tid * 4];
    float4 f;
    f.x = xa.x - sw * c.x; f.y = xa.y - sw * c.y;
    f.z = xa.z - sw * c.z; f.w = xa.w - sw * c.w;
    float ss = f.x * f.x + f.y * f.y + f.z * f.z + f.w * f.w;
#pragma unroll
    for (int off = 16; off > 0; off >>= 1)
        ss += __shfl_xor_sync(0xffffffffu, ss, off);

    __shared__ float wsum[4];
    __shared__ float scale_s;
    if ((tid & 31) == 0) wsum[tid >> 5] = ss;
    __syncthreads();
    if (tid == 0) {
        float tot = wsum[0] + wsum[1] + wsum[2] + wsum[3];
        float sc = rsqrtf(fmaxf(tot, F_EPS));
        scale_s = sc;
        atomicAdd(&g_norm2[b], tot * sc * sc);
    }
    __syncthreads();
    float sc = scale_s;
    float v0 = f.x * sc, v1 = f.y * sc, v2 = f.z * sc, v3 = f.w * sc;
    float h0 = tf32_rna(v0), h1 = tf32_rna(v1), h2 = tf32_rna(v2), h3 = tf32_rna(v3);
    size_t col = (size_t)k * DD + tid * 4;
    *(float4*)&g_v64[(size_t)b * KD + col] = make_float4(h0, h1, h2, h3);
    *(float4*)&g_v64[(size_t)(b + 32) * KD + col] =
        make_float4(v0 - h0, v1 - h1, v2 - h2, v3 - h3);
}

// ---------------------------------------------------------------------------
// K4: out = v @ R via mma.sync m16n8k8 tf32 (baseline PTX, no 'a' feature).
// Block: 32b x 128o, 1024-kd split, chunks of 32 kd. 4 warps: warp w covers
// m-half (w&1)*16 and n-range (w>>1)*64 (8 n8 tiles). hi+lo rows accumulate
// into the same fp32 C fragments. grid: 8 o-tiles x 32 kd-splits = 256.
// ---------------------------------------------------------------------------
__global__ __launch_bounds__(128) void k_out_mma(const float* __restrict__ R,
                                                 float* __restrict__ out) {
    __shared__ __align__(16) float sV[64 * 36];    // [row 0-63][32 kd], pad 36
    __shared__ __align__(16) float sR[32 * 136];   // [kd][128 o], pad 136

    const int tid = threadIdx.x;
    const int lane = tid & 31, warp = tid >> 5;
    const int grp = lane >> 2, qid = lane & 3;
    const int mh = (warp & 1) * 16;
    const int nb = (warp >> 1) * 64;
    const int o0 = (blockIdx.x & 7) * 128;
    const int kd_base = (blockIdx.x >> 3) * 1024;

    float C[8][4];
#pragma unroll
    for (int j = 0; j < 8; j++)
#pragma unroll
        for (int q = 0; q < 4; q++) C[j][q] = 0.0f;

    const float4* R4 = (const float4*)R;
    const float4* V4 = (const float4*)g_v64;
    float4 pB[8], pA[4];

#define K4_LDG(cc)                                                                \
    do {                                                                          \
        _Pragma("unroll")                                                         \
        for (int i_ = 0; i_ < 8; i_++) {                                          \
            int idx = tid + i_ * 128;                                             \
            pB[i_] = R4[(size_t)(kd_base + (cc) * 32 + (idx >> 5)) * 256          \
                        + (o0 >> 2) + (idx & 31)];                                \
        }                                                                         \
        _Pragma("unroll")                                                         \
        for (int i_ = 0; i_ < 4; i_++) {                                          \
            int idx = tid + i_ * 128;                                             \
            pA[i_] = V4[(size_t)(idx >> 3) * (KD / 4)                             \
                        + ((kd_base + (cc) * 32) >> 2) + (idx & 7)];              \
        }                                                                         \
    } while (0)
#define K4_STS()                                                                  \
    do {                                                                          \
        _Pragma("unroll")                                                         \
        for (int i_ = 0; i_ < 8; i_++) {                                          \
            int idx = tid + i_ * 128;                                             \
            *(float4*)&sR[(idx >> 5) * 136 + (idx & 31) * 4] = pB[i_];            \
        }                                                                         \
        _Pragma("unroll")                                                         \
        for (int i_ = 0; i_ < 4; i_++) {                                          \
            int idx = tid + i_ * 128;                                             \
            *(float4*)&sV[(idx >> 3) * 36 + (idx & 7) * 4] = pA[i_];              \
        }                                                                         \
    } while (0)

    K4_LDG(0);
    K4_STS();
    __syncthreads();

    const int NC = 32;
    for (int c = 0; c < NC; c++) {
        if (c + 1 < NC) K4_LDG(c + 1);

#pragma unroll
        for (int ks = 0; ks < 4; ks++) {
            const int k0 = ks * 8;
            unsigned ah[4], al[4];
            ah[0] = __float_as_uint(sV[(mh + grp) * 36 + k0 + qid]);
            ah[1] = __float_as_uint(sV[(mh + grp + 8) * 36 + k0 + qid]);
            ah[2] = __float_as_uint(sV[(mh + grp) * 36 + k0 + qid + 4]);
            ah[3] = __float_as_uint(sV[(mh + grp + 8) * 36 + k0 + qid + 4]);
            al[0] = __float_as_uint(sV[(32 + mh + grp) * 36 + k0 + qid]);
            al[1] = __float_as_uint(sV[(32 + mh + grp + 8) * 36 + k0 + qid]);
            al[2] = __float_as_uint(sV[(32 + mh + grp) * 36 + k0 + qid + 4]);
            al[3] = __float_as_uint(sV[(32 + mh + grp + 8) * 36 + k0 + qid + 4]);
#pragma unroll
            for (int j = 0; j < 8; j++) {
                const int n = nb + j * 8 + grp;
                unsigned b0 = __float_as_uint(sR[(k0 + qid) * 136 + n]);
                unsigned b1 = __float_as_uint(sR[(k0 + qid + 4) * 136 + n]);
                asm volatile(
                    "mma.sync.aligned.m16n8k8.row.col.f32.tf32.tf32.f32 "
                    "{%0,%1,%2,%3}, {%4,%5,%6,%7}, {%8,%9}, {%0,%1,%2,%3};"
                    : "+f"(C[j][0]), "+f"(C[j][1]), "+f"(C[j][2]), "+f"(C[j][3])
                    : "r"(ah[0]), "r"(ah[1]), "r"(ah[2]), "r"(ah[3]),
                      "r"(b0), "r"(b1));
                asm volatile(
                    "mma.sync.aligned.m16n8k8.row.col.f32.tf32.tf32.f32 "
                    "{%0,%1,%2,%3}, {%4,%5,%6,%7}, {%8,%9}, {%0,%1,%2,%3};"
                    : "+f"(C[j][0]), "+f"(C[j][1]), "+f"(C[j][2]), "+f"(C[j][3])
                    : "r"(al[0]), "r"(al[1]), "r"(al[2]), "r"(al[3]),
                      "r"(b0), "r"(b1));
            }
        }
        __syncthreads();
        if (c + 1 < NC) {
            K4_STS();
            __syncthreads();
        }
    }
#undef K4_LDG
#undef K4_STS

    const int row0 = mh + grp;
#pragma unroll
    for (int j = 0; j < 8; j++) {
        const int col = o0 + nb + j * 8 + qid * 2;
        atomicAdd(&out[(size_t)row0 * OO + col], C[j][0]);
        atomicAdd(&out[(size_t)row0 * OO + col + 1], C[j][1]);
        atomicAdd(&out[(size_t)(row0 + 8) * OO + col], C[j][2]);
        atomicAdd(&out[(size_t)(row0 + 8) * OO + col + 1], C[j][3]);
    }
}

__global__ __launch_bounds__(256) void k_finish(float* __restrict__ out) {
    int i = blockIdx.x * 256 + threadIdx.x;
    int b = i >> 10;
    out[i] *= rsqrtf(fmaxf(g_norm2[b], F_EPS));
}

extern "C" void kernel_launch(void* const* d_in, const int* in_sizes, int n_in,
                              void* d_out, int out_size) {
    const float* x       = (const float*)d_in[0];
    const float* w       = (const float*)d_in[1];
    const float* bias    = (const float*)d_in[2];
    const float* centers = (const float*)d_in[3];
    const float* R       = (const float*)d_in[4];
    float* out = (float*)d_out;

    void *p_agg, *p_sumw, *p_norm2;
    cudaGetSymbolAddress(&p_agg, g_agg);
    cudaGetSymbolAddress(&p_sumw, g_sumw);
    cudaGetSymbolAddress(&p_norm2, g_norm2);

    cudaMemsetAsync(p_agg, 0, sizeof(float) * BB * KK * DD);
    cudaMemsetAsync(p_sumw, 0, sizeof(float) * BB * KK);
    cudaMemsetAsync(p_norm2, 0, sizeof(float) * BB);
    cudaMemsetAsync(d_out, 0, sizeof(float) * BB * OO);

    k_assign<<<256, 128>>>(x, w, bias);
    k_agg<<<256, 128>>>(x);
    k_norm<<<2048, 128>>>(centers);
    k_out_mma<<<256, 128>>>(R, out);
    k_finish<<<128, 256>>>(out);
}

// round 10
// speedup vs baseline: 1.8887x; 1.3462x over previous
#include <cuda_runtime.h>
#include <math.h>

#define BB 32
#define TT 1024
#define DD 512
#define KK 64
#define OO 1024
#define KD (KK * DD)
#define F_EPS 1e-12f

typedef unsigned long long ull;

__device__ __forceinline__ float tf32_rna(float v) {
    float h; asm("cvt.rna.tf32.f32 %0, %1;" : "=f"(h) : "f"(v)); return h;
}

#define MMA8(Cp, a0, a1, a2, a3, b0, b1)                                        \
    asm volatile(                                                               \
        "mma.sync.aligned.m16n8k8.row.col.f32.tf32.tf32.f32 "                   \
        "{%0,%1,%2,%3}, {%4,%5,%6,%7}, {%8,%9}, {%0,%1,%2,%3};"                 \
        : "+f"((Cp)[0]), "+f"((Cp)[1]), "+f"((Cp)[2]), "+f"((Cp)[3])            \
        : "r"(a0), "r"(a1), "r"(a2), "r"(a3), "r"(b0), "r"(b1))

__device__ float g_a[BB * TT * KK];
__device__ float g_agg[BB * KK * DD];
__device__ float g_v64[64 * KD];     // rows 0-31: tf32-hi(v) per b; rows 32-63: residual
__device__ float g_sumw[BB * KK];
__device__ float g_norm2[BB];

// ---------------------------------------------------------------------------
// K1: logits = x@W + bias -> softmax -> a, sum_w.  mma tf32, 3-product split.
// Block: 128 rows x 64 k. Warp w: rows w*32..+32 (2 m16 tiles), all 8 n8 tiles.
// ---------------------------------------------------------------------------
__global__ __launch_bounds__(128) void k_assign_mma(const float* __restrict__ x,
                                                    const float* __restrict__ w,
                                                    const float* __restrict__ bias) {
    __shared__ __align__(16) float sX[128 * 36];   // [row][32 d]
    __shared__ __align__(16) float sW[32 * 72];    // [d][64 k]
    __shared__ float bias_s[64];
    __shared__ float ssum[64];

    const int tid = threadIdx.x;
    const int lane = tid & 31, warp = tid >> 5;
    const int grp = lane >> 2, qid = lane & 3;
    const int r0 = blockIdx.x * 128;
    const int b = r0 >> 10;

    if (tid < 64) { ssum[tid] = 0.0f; bias_s[tid] = bias[tid]; }

    float C[2][8][4];
#pragma unroll
    for (int t = 0; t < 2; t++)
#pragma unroll
        for (int j = 0; j < 8; j++)
#pragma unroll
            for (int q = 0; q < 4; q++) C[t][j][q] = 0.0f;

    float4 pX[8], pW[4];

#define K1_LDG(c0)                                                              \
    do {                                                                        \
        _Pragma("unroll")                                                       \
        for (int i_ = 0; i_ < 8; i_++) {                                        \
            int idx = tid + i_ * 128;                                           \
            pX[i_] = *(const float4*)&x[(size_t)(r0 + (idx >> 3)) * DD + (c0)   \
                                        + (idx & 7) * 4];                       \
        }                                                                       \
        _Pragma("unroll")                                                       \
        for (int i_ = 0; i_ < 4; i_++) {                                        \
            int idx = tid + i_ * 128;                                           \
            pW[i_] = *(const float4*)&w[(size_t)((c0) + (idx >> 4)) * KK        \
                                        + (idx & 15) * 4];                      \
        }                                                                       \
    } while (0)
#define K1_STS()                                                                \
    do {                                                                        \
        _Pragma("unroll")                                                       \
        for (int i_ = 0; i_ < 8; i_++) {                                        \
            int idx = tid + i_ * 128;                                           \
            *(float4*)&sX[(idx >> 3) * 36 + (idx & 7) * 4] = pX[i_];            \
        }                                                                       \
        _Pragma("unroll")                                                       \
        for (int i_ = 0; i_ < 4; i_++) {                                        \
            int idx = tid + i_ * 128;                                           \
            *(float4*)&sW[(idx >> 4) * 72 + (idx & 15) * 4] = pW[i_];           \
        }                                                                       \
    } while (0)

    K1_LDG(0);
    K1_STS();
    __syncthreads();

    const int NC = DD / 32;   // 16
    for (int c = 0; c < NC; c++) {
        if (c + 1 < NC) K1_LDG((c + 1) * 32);

#pragma unroll
        for (int ks = 0; ks < 4; ks++) {
            const int k0 = ks * 8;
            unsigned ah[2][4], al[2][4];
#pragma unroll
            for (int t = 0; t < 2; t++) {
                const int base = warp * 32 + t * 16;
                float v0 = sX[(base + grp) * 36 + k0 + qid];
                float v1 = sX[(base + grp + 8) * 36 + k0 + qid];
                float v2 = sX[(base + grp) * 36 + k0 + qid + 4];
                float v3 = sX[(base + grp + 8) * 36 + k0 + qid + 4];
                float h0 = tf32_rna(v0), h1 = tf32_rna(v1);
                float h2 = tf32_rna(v2), h3 = tf32_rna(v3);
                ah[t][0] = __float_as_uint(h0); al[t][0] = __float_as_uint(v0 - h0);
                ah[t][1] = __float_as_uint(h1); al[t][1] = __float_as_uint(v1 - h1);
                ah[t][2] = __float_as_uint(h2); al[t][2] = __float_as_uint(v2 - h2);
                ah[t][3] = __float_as_uint(h3); al[t][3] = __float_as_uint(v3 - h3);
            }
#pragma unroll
            for (int j = 0; j < 8; j++) {
                const int n = j * 8 + grp;
                float b0f = sW[(k0 + qid) * 72 + n];
                float b1f = sW[(k0 + qid + 4) * 72 + n];
                float bh0f = tf32_rna(b0f), bh1f = tf32_rna(b1f);
                unsigned bh0 = __float_as_uint(bh0f), bh1 = __float_as_uint(bh1f);
                unsigned bl0 = __float_as_uint(b0f - bh0f);
                unsigned bl1 = __float_as_uint(b1f - bh1f);
#pragma unroll
                for (int t = 0; t < 2; t++) {
                    MMA8(C[t][j], ah[t][0], ah[t][1], ah[t][2], ah[t][3], bh0, bh1);
                    MMA8(C[t][j], ah[t][0], ah[t][1], ah[t][2], ah[t][3], bl0, bl1);
                    MMA8(C[t][j], al[t][0], al[t][1], al[t][2], al[t][3], bh0, bh1);
                }
            }
        }
        __syncthreads();
        if (c + 1 < NC) {
            K1_STS();
            __syncthreads();
        }
    }
#undef K1_LDG
#undef K1_STS

    // softmax per row + a write + sum_w
    float cs[8][2];
#pragma unroll
    for (int j = 0; j < 8; j++) { cs[j][0] = 0.0f; cs[j][1] = 0.0f; }

#pragma unroll
    for (int t = 0; t < 2; t++) {
#pragma unroll
        for (int s = 0; s < 2; s++) {
            float va[8], vb[8];
            float m = -1e30f;
#pragma unroll
            for (int j = 0; j < 8; j++) {
                va[j] = C[t][j][s * 2 + 0] + bias_s[j * 8 + qid * 2];
                vb[j] = C[t][j][s * 2 + 1] + bias_s[j * 8 + qid * 2 + 1];
                m = fmaxf(m, fmaxf(va[j], vb[j]));
            }
            m = fmaxf(m, __shfl_xor_sync(0xffffffffu, m, 1));
            m = fmaxf(m, __shfl_xor_sync(0xffffffffu, m, 2));
            float sm = 0.0f;
#pragma unroll
            for (int j = 0; j < 8; j++) {
                va[j] = __expf(va[j] - m);
                vb[j] = __expf(vb[j] - m);
                sm += va[j] + vb[j];
            }
            sm += __shfl_xor_sync(0xffffffffu, sm, 1);
            sm += __shfl_xor_sync(0xffffffffu, sm, 2);
            float inv = 1.0f / sm;
            const int row = r0 + warp * 32 + t * 16 + s * 8 + grp;
#pragma unroll
            for (int j = 0; j < 8; j++) {
                float2 o;
                o.x = va[j] * inv; o.y = vb[j] * inv;
                *(float2*)&g_a[(size_t)row * KK + j * 8 + qid * 2] = o;
                cs[j][0] += o.x; cs[j][1] += o.y;
            }
        }
    }
#pragma unroll
    for (int j = 0; j < 8; j++) {
#pragma unroll
        for (int off = 4; off < 32; off <<= 1) {
            cs[j][0] += __shfl_xor_sync(0xffffffffu, cs[j][0], off);
            cs[j][1] += __shfl_xor_sync(0xffffffffu, cs[j][1], off);
        }
    }
    if (grp == 0) {
#pragma unroll
        for (int j = 0; j < 8; j++) {
            atomicAdd(&ssum[j * 8 + qid * 2], cs[j][0]);
            atomicAdd(&ssum[j * 8 + qid * 2 + 1], cs[j][1]);
        }
    }
    __syncthreads();
    if (tid < 64) atomicAdd(&g_sumw[b * KK + tid], ssum[tid]);
}

// ---------------------------------------------------------------------------
// K2: x_agg[b,k,d] = sum_t a[b,t,k] x[b,t,d].  mma tf32, 3-product split.
// C[64 k][128 d] per block; A = a^T (m=center, kdim=t), B = x (t x d).
// grid: b(32) x dtile(4) x tseg(2) = 256 blocks; 512 t per block, chunk 32.
// ---------------------------------------------------------------------------
__global__ __launch_bounds__(128) void k_agg_mma(const float* __restrict__ x) {
    __shared__ __align__(16) float sA[32 * 72];     // [t][64 k]
    __shared__ __align__(16) float sX2[32 * 136];   // [t][128 d]

    const int tid = threadIdx.x;
    const int lane = tid & 31, warp = tid >> 5;
    const int grp = lane >> 2, qid = lane & 3;
    const int bx = blockIdx.x;
    const int b   = bx >> 3;
    const int dt  = (bx >> 1) & 3;
    const int seg = bx & 1;
    const int t0  = seg * 512;
    const int nb  = warp * 32;   // d-range within the 128-d tile

    float C[4][4][4];
#pragma unroll
    for (int mt = 0; mt < 4; mt++)
#pragma unroll
        for (int j = 0; j < 4; j++)
#pragma unroll
            for (int q = 0; q < 4; q++) C[mt][j][q] = 0.0f;

    float4 pA[4], pX[8];

#define K2_LDG(tc)                                                              \
    do {                                                                        \
        _Pragma("unroll")                                                       \
        for (int i_ = 0; i_ < 4; i_++) {                                        \
            int idx = tid + i_ * 128;                                           \
            pA[i_] = *(const float4*)&g_a[(size_t)(b * TT + t0 + (tc) * 32      \
                                        + (idx >> 4)) * KK + (idx & 15) * 4];   \
        }                                                                       \
        _Pragma("unroll")                                                       \
        for (int i_ = 0; i_ < 8; i_++) {                                        \
            int idx = tid + i_ * 128;                                           \
            pX[i_] = *(const float4*)&x[(size_t)(b * TT + t0 + (tc) * 32        \
                                        + (idx >> 5)) * DD + dt * 128           \
                                        + (idx & 31) * 4];                      \
        }                                                                       \
    } while (0)
#define K2_STS()                                                                \
    do {                                                                        \
        _Pragma("unroll")                                                       \
        for (int i_ = 0; i_ < 4; i_++) {                                        \
            int idx = tid + i_ * 128;                                           \
            *(float4*)&sA[(idx >> 4) * 72 + (idx & 15) * 4] = pA[i_];           \
        }                                                                       \
        _Pragma("unroll")                                                       \
        for (int i_ = 0; i_ < 8; i_++) {                                        \
            int idx = tid + i_ * 128;                                           \
            *(float4*)&sX2[(idx >> 5) * 136 + (idx & 31) * 4] = pX[i_];         \
        }                                                                       \
    } while (0)

    K2_LDG(0);
    K2_STS();
    __syncthreads();

    const int NC = 16;   // 16 chunks x 32 t = 512 t
    for (int c = 0; c < NC; c++) {
        if (c + 1 < NC) K2_LDG(c + 1);

#pragma unroll
        for (int ks = 0; ks < 4; ks++) {
            const int k0 = ks * 8;
            unsigned ah[4][4], al[4][4];
#pragma unroll
            for (int mt = 0; mt < 4; mt++) {
                const int m0 = mt * 16;
                float v0 = sA[(k0 + qid) * 72 + m0 + grp];
                float v1 = sA[(k0 + qid) * 72 + m0 + grp + 8];
                float v2 = sA[(k0 + qid + 4) * 72 + m0 + grp];
                float v3 = sA[(k0 + qid + 4) * 72 + m0 + grp + 8];
                float h0 = tf32_rna(v0), h1 = tf32_rna(v1);
                float h2 = tf32_rna(v2), h3 = tf32_rna(v3);
                ah[mt][0] = __float_as_uint(h0); al[mt][0] = __float_as_uint(v0 - h0);
                ah[mt][1] = __float_as_uint(h1); al[mt][1] = __float_as_uint(v1 - h1);
                ah[mt][2] = __float_as_uint(h2); al[mt][2] = __float_as_uint(v2 - h2);
                ah[mt][3] = __float_as_uint(h3); al[mt][3] = __float_as_uint(v3 - h3);
            }
#pragma unroll
            for (int j = 0; j < 4; j++) {
                const int n = nb + j * 8 + grp;
                float b0f = sX2[(k0 + qid) * 136 + n];
                float b1f = sX2[(k0 + qid + 4) * 136 + n];
                float bh0f = tf32_rna(b0f), bh1f = tf32_rna(b1f);
                unsigned bh0 = __float_as_uint(bh0f), bh1 = __float_as_uint(bh1f);
                unsigned bl0 = __float_as_uint(b0f - bh0f);
                unsigned bl1 = __float_as_uint(b1f - bh1f);
#pragma unroll
                for (int mt = 0; mt < 4; mt++) {
                    MMA8(C[mt][j], ah[mt][0], ah[mt][1], ah[mt][2], ah[mt][3], bh0, bh1);
                    MMA8(C[mt][j], ah[mt][0], ah[mt][1], ah[mt][2], ah[mt][3], bl0, bl1);
                    MMA8(C[mt][j], al[mt][0], al[mt][1], al[mt][2], al[mt][3], bh0, bh1);
                }
            }
        }
        __syncthreads();
        if (c + 1 < NC) {
            K2_STS();
            __syncthreads();
        }
    }
#undef K2_LDG
#undef K2_STS

#pragma unroll
    for (int mt = 0; mt < 4; mt++)
#pragma unroll
        for (int j = 0; j < 4; j++) {
            const int center = mt * 16 + grp;
            const int d = dt * 128 + nb + j * 8 + qid * 2;
            atomicAdd(&g_agg[((size_t)b * KK + center) * DD + d],     C[mt][j][0]);
            atomicAdd(&g_agg[((size_t)b * KK + center) * DD + d + 1], C[mt][j][1]);
            atomicAdd(&g_agg[((size_t)b * KK + center + 8) * DD + d],     C[mt][j][2]);
            atomicAdd(&g_agg[((size_t)b * KK + center + 8) * DD + d + 1], C[mt][j][3]);
        }
}

// K3: residual + intra-normalize; write tf32-hi / residual split rows of v
__global__ __launch_bounds__(128) void k_norm(const float* __restrict__ centers) {
    const int bx = blockIdx.x;
    const int b = bx >> 6;
    const int k = bx & 63;
    const int tid = threadIdx.x;

    const float sw = g_sumw[b * KK + k];
    const size_t base = ((size_t)b * KK + k) * DD;

    float4 xa = *(float4*)&g_agg[base + tid * 4];
    float4 c  = *(const float4*)&centers[(size_t)k * DD + tid * 4];
    float4 f;
    f.x = xa.x - sw * c.x; f.y = xa.y - sw * c.y;
    f.z = xa.z - sw * c.z; f.w = xa.w - sw * c.w;
    float ss = f.x * f.x + f.y * f.y + f.z * f.z + f.w * f.w;
#pragma unroll
    for (int off = 16; off > 0; off >>= 1)
        ss += __shfl_xor_sync(0xffffffffu, ss, off);

    __shared__ float wsum[4];
    __shared__ float scale_s;
    if ((tid & 31) == 0) wsum[tid >> 5] = ss;
    __syncthreads();
    if (tid == 0) {
        float tot = wsum[0] + wsum[1] + wsum[2] + wsum[3];
        float sc = rsqrtf(fmaxf(tot, F_EPS));
        scale_s = sc;
        atomicAdd(&g_norm2[b], tot * sc * sc);
    }
    __syncthreads();
    float sc = scale_s;
    float v0 = f.x * sc, v1 = f.y * sc, v2 = f.z * sc, v3 = f.w * sc;
    float h0 = tf32_rna(v0), h1 = tf32_rna(v1), h2 = tf32_rna(v2), h3 = tf32_rna(v3);
    size_t col = (size_t)k * DD + tid * 4;
    *(float4*)&g_v64[(size_t)b * KD + col] = make_float4(h0, h1, h2, h3);
    *(float4*)&g_v64[(size_t)(b + 32) * KD + col] =
        make_float4(v0 - h0, v1 - h1, v2 - h2, v3 - h3);
}

// ---------------------------------------------------------------------------
// K4: out = v @ R via mma.sync tf32 (R9 proven). kd-split 64 -> 512 CTAs.
// ---------------------------------------------------------------------------
__global__ __launch_bounds__(128) void k_out_mma(const float* __restrict__ R,
                                                 float* __restrict__ out) {
    __shared__ __align__(16) float sV[64 * 36];
    __shared__ __align__(16) float sR[32 * 136];

    const int tid = threadIdx.x;
    const int lane = tid & 31, warp = tid >> 5;
    const int grp = lane >> 2, qid = lane & 3;
    const int mh = (warp & 1) * 16;
    const int nb = (warp >> 1) * 64;
    const int o0 = (blockIdx.x & 7) * 128;
    const int kd_base = (blockIdx.x >> 3) * 512;

    float C[8][4];
#pragma unroll
    for (int j = 0; j < 8; j++)
#pragma unroll
        for (int q = 0; q < 4; q++) C[j][q] = 0.0f;

    const float4* R4 = (const float4*)R;
    const float4* V4 = (const float4*)g_v64;
    float4 pB[8], pA[4];

#define K4_LDG(cc)                                                                \
    do {                                                                          \
        _Pragma("unroll")                                                         \
        for (int i_ = 0; i_ < 8; i_++) {                                          \
            int idx = tid + i_ * 128;                                             \
            pB[i_] = R4[(size_t)(kd_base + (cc) * 32 + (idx >> 5)) * 256          \
                        + (o0 >> 2) + (idx & 31)];                                \
        }                                                                         \
        _Pragma("unroll")                                                         \
        for (int i_ = 0; i_ < 4; i_++) {                                          \
            int idx = tid + i_ * 128;                                             \
            pA[i_] = V4[(size_t)(idx >> 3) * (KD / 4)                             \
                        + ((kd_base + (cc) * 32) >> 2) + (idx & 7)];              \
        }                                                                         \
    } while (0)
#define K4_STS()                                                                  \
    do {                                                                          \
        _Pragma("unroll")                                                         \
        for (int i_ = 0; i_ < 8; i_++) {                                          \
            int idx = tid + i_ * 128;                                             \
            *(float4*)&sR[(idx >> 5) * 136 + (idx & 31) * 4] = pB[i_];            \
        }                                                                         \
        _Pragma("unroll")                                                         \
        for (int i_ = 0; i_ < 4; i_++) {                                          \
            int idx = tid + i_ * 128;                                             \
            *(float4*)&sV[(idx >> 3) * 36 + (idx & 7) * 4] = pA[i_];              \
        }                                                                         \
    } while (0)

    K4_LDG(0);
    K4_STS();
    __syncthreads();

    const int NC = 16;
    for (int c = 0; c < NC; c++) {
        if (c + 1 < NC) K4_LDG(c + 1);

#pragma unroll
        for (int ks = 0; ks < 4; ks++) {
            const int k0 = ks * 8;
            unsigned ah[4], al[4];
            ah[0] = __float_as_uint(sV[(mh + grp) * 36 + k0 + qid]);
            ah[1] = __float_as_uint(sV[(mh + grp + 8) * 36 + k0 + qid]);
            ah[2] = __float_as_uint(sV[(mh + grp) * 36 + k0 + qid + 4]);
            ah[3] = __float_as_uint(sV[(mh + grp + 8) * 36 + k0 + qid + 4]);
            al[0] = __float_as_uint(sV[(32 + mh + grp) * 36 + k0 + qid]);
            al[1] = __float_as_uint(sV[(32 + mh + grp + 8) * 36 + k0 + qid]);
            al[2] = __float_as_uint(sV[(32 + mh + grp) * 36 + k0 + qid + 4]);
            al[3] = __float_as_uint(sV[(32 + mh + grp + 8) * 36 + k0 + qid + 4]);
#pragma unroll
            for (int j = 0; j < 8; j++) {
                const int n = nb + j * 8 + grp;
                unsigned b0 = __float_as_uint(sR[(k0 + qid) * 136 + n]);
                unsigned b1 = __float_as_uint(sR[(k0 + qid + 4) * 136 + n]);
                MMA8(C[j], ah[0], ah[1], ah[2], ah[3], b0, b1);
                MMA8(C[j], al[0], al[1], al[2], al[3], b0, b1);
            }
        }
        __syncthreads();
        if (c + 1 < NC) {
            K4_STS();
            __syncthreads();
        }
    }
#undef K4_LDG
#undef K4_STS

    const int row0 = mh + grp;
#pragma unroll
    for (int j = 0; j < 8; j++) {
        const int col = o0 + nb + j * 8 + qid * 2;
        atomicAdd(&out[(size_t)row0 * OO + col], C[j][0]);
        atomicAdd(&out[(size_t)row0 * OO + col + 1], C[j][1]);
        atomicAdd(&out[(size_t)(row0 + 8) * OO + col], C[j][2]);
        atomicAdd(&out[(size_t)(row0 + 8) * OO + col + 1], C[j][3]);
    }
}

__global__ __launch_bounds__(256) void k_finish(float* __restrict__ out) {
    int i = blockIdx.x * 256 + threadIdx.x;
    int b = i >> 10;
    out[i] *= rsqrtf(fmaxf(g_norm2[b], F_EPS));
}

extern "C" void kernel_launch(void* const* d_in, const int* in_sizes, int n_in,
                              void* d_out, int out_size) {
    const float* x       = (const float*)d_in[0];
    const float* w       = (const float*)d_in[1];
    const float* bias    = (const float*)d_in[2];
    const float* centers = (const float*)d_in[3];
    const float* R       = (const float*)d_in[4];
    float* out = (float*)d_out;

    void *p_agg, *p_sumw, *p_norm2;
    cudaGetSymbolAddress(&p_agg, g_agg);
    cudaGetSymbolAddress(&p_sumw, g_sumw);
    cudaGetSymbolAddress(&p_norm2, g_norm2);

    cudaMemsetAsync(p_agg, 0, sizeof(float) * BB * KK * DD);
    cudaMemsetAsync(p_sumw, 0, sizeof(float) * BB * KK);
    cudaMemsetAsync(p_norm2, 0, sizeof(float) * BB);
    cudaMemsetAsync(d_out, 0, sizeof(float) * BB * OO);

    k_assign_mma<<<256, 128>>>(x, w, bias);
    k_agg_mma<<<256, 128>>>(x);
    k_norm<<<2048, 128>>>(centers);
    k_out_mma<<<512, 128>>>(R, out);
    k_finish<<<128, 256>>>(out);
}